// round 11
// baseline (speedup 1.0000x reference)
#include <cuda_runtime.h>
#include <cuda_fp16.h>

#define NROWS 16384
#define NCOL  1024
#define NPAIR (NROWS / 2)     /* 8192 row pairs */
#define NTHR  256
#define NWARP (NTHR / 32)
#define GRID  444             /* 148 SMs x 3 CTAs, persistent */
#define NIT   20
#define CSS   64              /* colsum counter stride in floats (256 B) */
#define THR   0.05f           /* ALPHA*LAMBD/RHO */
#define SHRK  0.05f           /* (1-ALPHA)*LAMBD */
#define EPSI  1e-10f
#define SQMIN 1e-20f          /* sqrt(MIN_VALUE) */

__device__ __half g_u[NROWS * NCOL];                 /* fp16 u_k = R_k + Z_{k-1} */
__device__ __half g_h[NROWS * NCOL];                 /* fp16 sqrt(R_0c) */
__device__ float  g_cs[(size_t)NIT * NCOL * CSS];

__global__ void k_zero() {
    g_cs[((size_t)blockIdx.x * NCOL + threadIdx.x) * CSS] = 0.0f;
}

/* single-MUFU sqrt; sqrt.approx.f32(0) == 0 exactly (PTX ISA) */
__device__ __forceinline__ float sqrt_ap(float x) {
    float r;
    asm("sqrt.approx.f32 %0, %1;" : "=f"(r) : "f"(x));
    return r;
}

/* soft threshold as x - clamp(x, -THR, THR): 3 ops, exact */
__device__ __forceinline__ float soft(float x) {
    return x - fminf(fmaxf(x, -THR), THR);
}

__device__ __forceinline__ float wredsum(float v) {
#pragma unroll
    for (int o = 16; o > 0; o >>= 1) v += __shfl_xor_sync(0xffffffffu, v, o);
    return v;
}

__device__ __forceinline__ void ld4h(const __half* p, float f[4]) {
    uint2 pk = *(const uint2*)p;
    __half2 a = *reinterpret_cast<__half2*>(&pk.x);
    __half2 b = *reinterpret_cast<__half2*>(&pk.y);
    float2 fa = __half22float2(a), fb = __half22float2(b);
    f[0] = fa.x; f[1] = fa.y; f[2] = fb.x; f[3] = fb.y;
}

__device__ __forceinline__ void st4h(__half* p, const float f[4]) {
    __half2 a = __floats2half2_rn(f[0], f[1]);
    __half2 b = __floats2half2_rn(f[2], f[3]);
    uint2 pk;
    pk.x = *reinterpret_cast<unsigned*>(&a);
    pk.y = *reinterpret_cast<unsigned*>(&b);
    *(uint2*)p = pk;
}

// u_1 = R_1 = R_0c / rowsum(R_0c)  (Z_0 = 0); writes fp16 u_1, fp16 sqrt(R_0c); colsum_1.
__global__ void __launch_bounds__(NTHR, 3) k_init(const float* __restrict__ r0) {
    __shared__ float sp[2][2][NWARP];
    const int tid  = threadIdx.x;
    const int lane = tid & 31;
    const int wid  = tid >> 5;
    const int col  = tid * 4;

    float c4[4] = {0.f, 0.f, 0.f, 0.f};

    float4 a0, a1, na0, na1;
    {
        const size_t b = (size_t)blockIdx.x * 2 * NCOL + col;
        a0 = *(const float4*)(r0 + b);
        a1 = *(const float4*)(r0 + b + NCOL);
    }

    int it = 0;
    for (int pair = blockIdx.x; pair < NPAIR; pair += GRID, ++it) {
        const int cur = it & 1;
        float v0[4] = {a0.x, a0.y, a0.z, a0.w};
        float v1[4] = {a1.x, a1.y, a1.z, a1.w};
#pragma unroll
        for (int j = 0; j < 4; ++j) {
            if (v0[j] == 0.0f) v0[j] = 1e-40f;
            if (v1[j] == 0.0f) v1[j] = 1e-40f;
        }
        float p0 = wredsum((v0[0] + v0[1]) + (v0[2] + v0[3]));
        float p1 = wredsum((v1[0] + v1[1]) + (v1[2] + v1[3]));
        if (lane == 0) { sp[cur][0][wid] = p0; sp[cur][1][wid] = p1; }

        int np = pair + GRID; if (np >= NPAIR) np = pair;   // safe redundant prefetch
        {
            const size_t nb = (size_t)np * 2 * NCOL + col;
            na0 = *(const float4*)(r0 + nb);
            na1 = *(const float4*)(r0 + nb + NCOL);
        }
        __syncthreads();
        float S0 = 0.f, S1 = 0.f;
#pragma unroll
        for (int w = 0; w < NWARP; ++w) { S0 += sp[cur][0][w]; S1 += sp[cur][1][w]; }
        const float i0 = __fdividef(1.0f, S0);
        const float i1 = __fdividef(1.0f, S1);

        const size_t base = (size_t)pair * 2 * NCOL + col;
        float r0n[4], r1n[4], q0[4], q1[4];
#pragma unroll
        for (int j = 0; j < 4; ++j) {
            r0n[j] = v0[j] * i0;     r1n[j] = v1[j] * i1;
            q0[j]  = sqrt_ap(v0[j]); q1[j] = sqrt_ap(v1[j]);
        }
        st4h(g_u + base,        r0n);
        st4h(g_u + base + NCOL, r1n);
        st4h(g_h + base,        q0);
        st4h(g_h + base + NCOL, q1);
#pragma unroll
        for (int j = 0; j < 4; ++j) {
            float s0 = soft(r0n[j]), s1 = soft(r1n[j]);
            c4[j] += s0 * s0 + s1 * s1;
        }
        a0 = na0; a1 = na1;
    }
#pragma unroll
    for (int j = 0; j < 4; ++j)
        atomicAdd(&g_cs[((size_t)1 * NCOL + col + j) * CSS], c4[j]);
}

// Step k: u_k -> u_{k+1}, colsum_{k+1}; last step writes fp32 R_20 to out.
// e = sqrt(r0c) * (sqrt_ap(X) + 1e-20) * exp(-z/2)
//   (X==0 -> exactly the reference MIN_VALUE branch since sqrt.approx(0)=0)
__global__ void __launch_bounds__(NTHR, 3) k_step(float* __restrict__ out,
                                                  int k, int rev, int last) {
    __shared__ float sp[2][2][NWARP];
    const int tid  = threadIdx.x;
    const int lane = tid & 31;
    const int wid  = tid >> 5;
    const int col  = tid * 4;

    float sc[4];
#pragma unroll
    for (int j = 0; j < 4; ++j) {
        float cs = g_cs[((size_t)k * NCOL + col + j) * CSS];
        sc[j] = fmaxf(1.0f - SHRK / (sqrtf(cs) + EPSI), 0.0f);
    }

    float c4[4] = {0.f, 0.f, 0.f, 0.f};
    float uu0[4], uu1[4], hh0[4], hh1[4];
    float nu0[4], nu1[4], nh0[4], nh1[4];

    int pair0 = rev ? (NPAIR - 1 - blockIdx.x) : blockIdx.x;
    {
        const size_t b = (size_t)pair0 * 2 * NCOL + col;
        ld4h(g_u + b, uu0);  ld4h(g_u + b + NCOL, uu1);
        ld4h(g_h + b, hh0);  ld4h(g_h + b + NCOL, hh1);
    }

    int it = 0;
    for (int w = blockIdx.x; w < NPAIR; w += GRID, ++it) {
        const int cur  = it & 1;
        const int pair = rev ? (NPAIR - 1 - w) : w;

        float e0[4], e1[4], zp0[4], zp1[4];
#pragma unroll
        for (int j = 0; j < 4; ++j) {
            float s  = soft(uu0[j]);
            float X  = sc[j] * s;
            zp0[j]   = uu0[j] - X;                          // Z_k
            float sx = sqrt_ap(X) + SQMIN;                  // branchless MIN_VALUE path
            e0[j]    = hh0[j] * sx * __expf(-0.5f * zp0[j]);
        }
#pragma unroll
        for (int j = 0; j < 4; ++j) {
            float s  = soft(uu1[j]);
            float X  = sc[j] * s;
            zp1[j]   = uu1[j] - X;
            float sx = sqrt_ap(X) + SQMIN;
            e1[j]    = hh1[j] * sx * __expf(-0.5f * zp1[j]);
        }
        float p0 = wredsum((e0[0] + e0[1]) + (e0[2] + e0[3]));
        float p1 = wredsum((e1[0] + e1[1]) + (e1[2] + e1[3]));
        if (lane == 0) { sp[cur][0][wid] = p0; sp[cur][1][wid] = p1; }

        int nw = w + GRID; if (nw >= NPAIR) nw = w;          // safe redundant prefetch
        {
            const int npair = rev ? (NPAIR - 1 - nw) : nw;
            const size_t nb = (size_t)npair * 2 * NCOL + col;
            ld4h(g_u + nb, nu0);  ld4h(g_u + nb + NCOL, nu1);
            ld4h(g_h + nb, nh0);  ld4h(g_h + nb + NCOL, nh1);
        }
        __syncthreads();
        float S0 = 0.f, S1 = 0.f;
#pragma unroll
        for (int ww = 0; ww < NWARP; ++ww) { S0 += sp[cur][0][ww]; S1 += sp[cur][1][ww]; }
        const float i0 = __fdividef(1.0f, S0);
        const float i1 = __fdividef(1.0f, S1);

        const size_t base = (size_t)pair * 2 * NCOL + col;
        float rn0[4], rn1[4];
#pragma unroll
        for (int j = 0; j < 4; ++j) { rn0[j] = e0[j] * i0; rn1[j] = e1[j] * i1; }

        if (last) {
            *(float4*)(out + base)        = make_float4(rn0[0], rn0[1], rn0[2], rn0[3]);
            *(float4*)(out + base + NCOL) = make_float4(rn1[0], rn1[1], rn1[2], rn1[3]);
        } else {
            float un0[4], un1[4];
#pragma unroll
            for (int j = 0; j < 4; ++j) {
                un0[j] = rn0[j] + zp0[j];                   // u_{k+1}
                un1[j] = rn1[j] + zp1[j];
                float s0 = soft(un0[j]), s1 = soft(un1[j]);
                c4[j] += s0 * s0 + s1 * s1;
            }
            st4h(g_u + base,        un0);
            st4h(g_u + base + NCOL, un1);
        }
#pragma unroll
        for (int j = 0; j < 4; ++j) {
            uu0[j] = nu0[j]; uu1[j] = nu1[j];
            hh0[j] = nh0[j]; hh1[j] = nh1[j];
        }
    }
    if (!last) {
#pragma unroll
        for (int j = 0; j < 4; ++j)
            atomicAdd(&g_cs[((size_t)(k + 1) * NCOL + col + j) * CSS], c4[j]);
    }
}

extern "C" void kernel_launch(void* const* d_in, const int* in_sizes, int n_in,
                              void* d_out, int out_size) {
    const float* r0 = (const float*)d_in[0];
    float* out = (float*)d_out;

    k_zero<<<NIT, NCOL>>>();
    k_init<<<GRID, NTHR>>>(r0);
    for (int k = 1; k < NIT; ++k)
        k_step<<<GRID, NTHR>>>(out, k, k & 1, (k == NIT - 1) ? 1 : 0);
}

// round 12
// speedup vs baseline: 1.0683x; 1.0683x over previous
#include <cuda_runtime.h>
#include <cuda_fp16.h>

#define NROWS 16384
#define NCOL  1024
#define NPAIR (NROWS / 2)     /* 8192 row pairs */
#define NTHR  256
#define NWARP (NTHR / 32)
#define GRID  592             /* 148 SMs x 4 CTAs, persistent */
#define NIT   20
#define CSS   64              /* colsum counter stride in floats (256 B) */
#define THR   0.05f           /* ALPHA*LAMBD/RHO */
#define SHRK  0.05f           /* (1-ALPHA)*LAMBD */
#define EPSI  1e-10f
#define SQMIN 1e-20f          /* sqrt(MIN_VALUE) */
#define PAD   (GRID * 2 * NCOL)   /* prefetch overshoot padding (elements) */

__device__ __half g_u[NROWS * NCOL + 2 * PAD];       /* fp16 u_k, padded both ends */
__device__ __half g_h[NROWS * NCOL + 2 * PAD];       /* fp16 sqrt(R_0c), padded */
__device__ float  g_cs[(size_t)NIT * NCOL * CSS];

__global__ void k_zero() {
    g_cs[((size_t)blockIdx.x * NCOL + threadIdx.x) * CSS] = 0.0f;
}

/* single-MUFU sqrt; sqrt.approx.f32(0) == 0 exactly (PTX ISA) */
__device__ __forceinline__ float sqrt_ap(float x) {
    float r;
    asm("sqrt.approx.f32 %0, %1;" : "=f"(r) : "f"(x));
    return r;
}

/* soft threshold as x - clamp(x, -THR, THR): 3 ops, exact */
__device__ __forceinline__ float soft(float x) {
    return x - fminf(fmaxf(x, -THR), THR);
}

__device__ __forceinline__ float wredsum(float v) {
#pragma unroll
    for (int o = 16; o > 0; o >>= 1) v += __shfl_xor_sync(0xffffffffu, v, o);
    return v;
}

__device__ __forceinline__ void cvt4(uint2 pk, float f[4]) {
    __half2 a = *reinterpret_cast<__half2*>(&pk.x);
    __half2 b = *reinterpret_cast<__half2*>(&pk.y);
    float2 fa = __half22float2(a), fb = __half22float2(b);
    f[0] = fa.x; f[1] = fa.y; f[2] = fb.x; f[3] = fb.y;
}

__device__ __forceinline__ void st4h(__half* p, const float f[4]) {
    __half2 a = __floats2half2_rn(f[0], f[1]);
    __half2 b = __floats2half2_rn(f[2], f[3]);
    uint2 pk;
    pk.x = *reinterpret_cast<unsigned*>(&a);
    pk.y = *reinterpret_cast<unsigned*>(&b);
    *(uint2*)p = pk;
}

// u_1 = R_1 = R_0c / rowsum(R_0c)  (Z_0 = 0); writes fp16 u_1, fp16 sqrt(R_0c); colsum_1.
__global__ void __launch_bounds__(NTHR, 4) k_init(const float* __restrict__ r0) {
    __shared__ float sp[2][2][NWARP];
    const int tid  = threadIdx.x;
    const int lane = tid & 31;
    const int wid  = tid >> 5;
    const int col  = tid * 4;

    float c4[4] = {0.f, 0.f, 0.f, 0.f};

    const int  niter = (NPAIR - blockIdx.x + GRID - 1) / GRID;
    const long long ds = (long long)GRID * 2 * NCOL;
    long long off = (long long)blockIdx.x * 2 * NCOL + col;

    float4 a0 = *(const float4*)(r0 + off);
    float4 a1 = *(const float4*)(r0 + off + NCOL);

    for (int i = 0; i < niter; ++i) {
        const int cur = i & 1;
        float v0[4] = {a0.x, a0.y, a0.z, a0.w};
        float v1[4] = {a1.x, a1.y, a1.z, a1.w};
#pragma unroll
        for (int j = 0; j < 4; ++j) {
            if (v0[j] == 0.0f) v0[j] = 1e-40f;
            if (v1[j] == 0.0f) v1[j] = 1e-40f;
        }
        float p0 = wredsum((v0[0] + v0[1]) + (v0[2] + v0[3]));
        float p1 = wredsum((v1[0] + v1[1]) + (v1[2] + v1[3]));
        if (lane == 0) { sp[cur][0][wid] = p0; sp[cur][1][wid] = p1; }

        if (i + 1 < niter) {        /* r0 has no padding — guard the prefetch */
            a0 = *(const float4*)(r0 + off + ds);
            a1 = *(const float4*)(r0 + off + ds + NCOL);
        }
        __syncthreads();
        float S0 = 0.f, S1 = 0.f;
#pragma unroll
        for (int w = 0; w < NWARP; ++w) { S0 += sp[cur][0][w]; S1 += sp[cur][1][w]; }
        const float i0 = __fdividef(1.0f, S0);
        const float i1 = __fdividef(1.0f, S1);

        float r0n[4], r1n[4], q0[4], q1[4];
#pragma unroll
        for (int j = 0; j < 4; ++j) {
            r0n[j] = v0[j] * i0;     r1n[j] = v1[j] * i1;
            q0[j]  = sqrt_ap(v0[j]); q1[j] = sqrt_ap(v1[j]);
        }
        st4h(g_u + PAD + off,        r0n);
        st4h(g_u + PAD + off + NCOL, r1n);
        st4h(g_h + PAD + off,        q0);
        st4h(g_h + PAD + off + NCOL, q1);
#pragma unroll
        for (int j = 0; j < 4; ++j) {
            float s0 = soft(r0n[j]), s1 = soft(r1n[j]);
            c4[j] += s0 * s0 + s1 * s1;
        }
        off += ds;
    }
#pragma unroll
    for (int j = 0; j < 4; ++j)
        atomicAdd(&g_cs[((size_t)1 * NCOL + col + j) * CSS], c4[j]);
}

// Step k: u_k -> u_{k+1}, colsum_{k+1}; LAST writes fp32 R_20 to out.
// e = sqrt(r0c) * (sqrt_ap(X) + 1e-20) * exp(-z/2)
template<int REV, int LAST>
__global__ void __launch_bounds__(NTHR, 4) k_step(float* __restrict__ out, int k) {
    __shared__ float sp[2][2][NWARP];
    const int tid  = threadIdx.x;
    const int lane = tid & 31;
    const int wid  = tid >> 5;
    const int col  = tid * 4;

    float sc[4];
#pragma unroll
    for (int j = 0; j < 4; ++j) {
        float cs = g_cs[((size_t)k * NCOL + col + j) * CSS];
        sc[j] = fmaxf(1.0f - SHRK / (sqrtf(cs) + EPSI), 0.0f);
    }

    float c4[4] = {0.f, 0.f, 0.f, 0.f};

    const int  pair0 = REV ? (NPAIR - 1 - blockIdx.x) : blockIdx.x;
    const int  niter = (NPAIR - blockIdx.x + GRID - 1) / GRID;
    const long long ds = (REV ? -(long long)GRID : (long long)GRID) * (2 * NCOL);
    long long off = (long long)pair0 * 2 * NCOL + col;

    const __half* pu = g_u + PAD;
    const __half* ph = g_h + PAD;

    uint2 ru0 = *(const uint2*)(pu + off);
    uint2 ru1 = *(const uint2*)(pu + off + NCOL);
    uint2 rh0 = *(const uint2*)(ph + off);
    uint2 rh1 = *(const uint2*)(ph + off + NCOL);

    for (int i = 0; i < niter; ++i) {
        const int cur = i & 1;

        float uu0[4], uu1[4], hh0[4], hh1[4];
        cvt4(ru0, uu0); cvt4(ru1, uu1);
        cvt4(rh0, hh0); cvt4(rh1, hh1);

        float e0[4], e1[4], zp0[4], zp1[4];
#pragma unroll
        for (int j = 0; j < 4; ++j) {
            float s  = soft(uu0[j]);
            float X  = sc[j] * s;
            zp0[j]   = uu0[j] - X;                          // Z_k
            float sx = sqrt_ap(X) + SQMIN;                  // branchless MIN_VALUE path
            e0[j]    = hh0[j] * sx * __expf(-0.5f * zp0[j]);
        }
#pragma unroll
        for (int j = 0; j < 4; ++j) {
            float s  = soft(uu1[j]);
            float X  = sc[j] * s;
            zp1[j]   = uu1[j] - X;
            float sx = sqrt_ap(X) + SQMIN;
            e1[j]    = hh1[j] * sx * __expf(-0.5f * zp1[j]);
        }
        float p0 = wredsum((e0[0] + e0[1]) + (e0[2] + e0[3]));
        float p1 = wredsum((e1[0] + e1[1]) + (e1[2] + e1[3]));
        if (lane == 0) { sp[cur][0][wid] = p0; sp[cur][1][wid] = p1; }

        /* unguarded prefetch — padding absorbs the final overshoot */
        ru0 = *(const uint2*)(pu + off + ds);
        ru1 = *(const uint2*)(pu + off + ds + NCOL);
        rh0 = *(const uint2*)(ph + off + ds);
        rh1 = *(const uint2*)(ph + off + ds + NCOL);

        __syncthreads();
        float S0 = 0.f, S1 = 0.f;
#pragma unroll
        for (int ww = 0; ww < NWARP; ++ww) { S0 += sp[cur][0][ww]; S1 += sp[cur][1][ww]; }
        const float i0 = __fdividef(1.0f, S0);
        const float i1 = __fdividef(1.0f, S1);

        float rn0[4], rn1[4];
#pragma unroll
        for (int j = 0; j < 4; ++j) { rn0[j] = e0[j] * i0; rn1[j] = e1[j] * i1; }

        if (LAST) {
            *(float4*)(out + off)        = make_float4(rn0[0], rn0[1], rn0[2], rn0[3]);
            *(float4*)(out + off + NCOL) = make_float4(rn1[0], rn1[1], rn1[2], rn1[3]);
        } else {
            float un0[4], un1[4];
#pragma unroll
            for (int j = 0; j < 4; ++j) {
                un0[j] = rn0[j] + zp0[j];                   // u_{k+1}
                un1[j] = rn1[j] + zp1[j];
                float s0 = soft(un0[j]), s1 = soft(un1[j]);
                c4[j] += s0 * s0 + s1 * s1;
            }
            st4h((__half*)(pu + off),        un0);
            st4h((__half*)(pu + off + NCOL), un1);
        }
        off += ds;
    }
    if (!LAST) {
#pragma unroll
        for (int j = 0; j < 4; ++j)
            atomicAdd(&g_cs[((size_t)(k + 1) * NCOL + col + j) * CSS], c4[j]);
    }
}

extern "C" void kernel_launch(void* const* d_in, const int* in_sizes, int n_in,
                              void* d_out, int out_size) {
    const float* r0 = (const float*)d_in[0];
    float* out = (float*)d_out;

    k_zero<<<NIT, NCOL>>>();
    k_init<<<GRID, NTHR>>>(r0);
    for (int k = 1; k < NIT; ++k) {
        const int rev  = k & 1;
        const int last = (k == NIT - 1);
        if (last) {
            if (rev) k_step<1, 1><<<GRID, NTHR>>>(out, k);
            else     k_step<0, 1><<<GRID, NTHR>>>(out, k);
        } else {
            if (rev) k_step<1, 0><<<GRID, NTHR>>>(out, k);
            else     k_step<0, 0><<<GRID, NTHR>>>(out, k);
        }
    }
}

// round 14
// speedup vs baseline: 1.0826x; 1.0134x over previous
#include <cuda_runtime.h>
#include <cuda_fp16.h>

#define NROWS 16384
#define NCOL  1024
#define NPAIR (NROWS / 2)     /* 8192 row pairs */
#define NTHR  256
#define NWARP (NTHR / 32)
#define GRID  592             /* 148 SMs x 4 CTAs, persistent */
#define NIT   20
#define CSS   64              /* colsum counter stride in floats (256 B) */
#define THR   0.05f           /* ALPHA*LAMBD/RHO */
#define SHRK  0.05f           /* (1-ALPHA)*LAMBD */
#define EPSI  1e-10f
#define SQMIN 1e-20f          /* sqrt(MIN_VALUE) */
#define K2E   (-0.72134752044448170f)  /* -0.5 * log2(e) */
#define PAD   (GRID * 2 * NCOL)   /* prefetch overshoot padding (elements) */

__device__ __half g_u[NROWS * NCOL + 2 * PAD];       /* fp16 u_k, padded both ends */
__device__ __half g_h[NROWS * NCOL + 2 * PAD];       /* fp16 sqrt(R_0c), padded */
__device__ float  g_cs[(size_t)NIT * NCOL * CSS];

__global__ void k_zero() {
    g_cs[((size_t)blockIdx.x * NCOL + threadIdx.x) * CSS] = 0.0f;
}

/* single-MUFU sqrt; sqrt.approx.f32(0) == 0 exactly (PTX ISA) */
__device__ __forceinline__ float sqrt_ap(float x) {
    float r;
    asm("sqrt.approx.f32 %0, %1;" : "=f"(r) : "f"(x));
    return r;
}

/* single-MUFU exp2 */
__device__ __forceinline__ float ex2(float x) {
    float r;
    asm("ex2.approx.f32 %0, %1;" : "=f"(r) : "f"(x));
    return r;
}

/* soft threshold as x - clamp(x, -THR, THR): 3 ops, exact */
__device__ __forceinline__ float soft(float x) {
    return x - fminf(fmaxf(x, -THR), THR);
}

__device__ __forceinline__ float wredsum(float v) {
#pragma unroll
    for (int o = 16; o > 0; o >>= 1) v += __shfl_xor_sync(0xffffffffu, v, o);
    return v;
}

__device__ __forceinline__ void cvt4(uint2 pk, float f[4]) {
    __half2 a = *reinterpret_cast<__half2*>(&pk.x);
    __half2 b = *reinterpret_cast<__half2*>(&pk.y);
    float2 fa = __half22float2(a), fb = __half22float2(b);
    f[0] = fa.x; f[1] = fa.y; f[2] = fb.x; f[3] = fb.y;
}

__device__ __forceinline__ void st4h(__half* p, const float f[4]) {
    __half2 a = __floats2half2_rn(f[0], f[1]);
    __half2 b = __floats2half2_rn(f[2], f[3]);
    uint2 pk;
    pk.x = *reinterpret_cast<unsigned*>(&a);
    pk.y = *reinterpret_cast<unsigned*>(&b);
    *(uint2*)p = pk;
}

// u_1 = R_1 = R_0c / rowsum(R_0c)  (Z_0 = 0); writes fp16 u_1, fp16 sqrt(R_0c); colsum_1.
__global__ void __launch_bounds__(NTHR, 4) k_init(const float* __restrict__ r0) {
    __shared__ float sp[2][2][NWARP];
    const int tid  = threadIdx.x;
    const int lane = tid & 31;
    const int wid  = tid >> 5;
    const int col  = tid * 4;

    float c4[4] = {0.f, 0.f, 0.f, 0.f};

    const int  niter = (NPAIR - blockIdx.x + GRID - 1) / GRID;
    const long long ds = (long long)GRID * 2 * NCOL;
    long long off = (long long)blockIdx.x * 2 * NCOL + col;

    float4 a0 = *(const float4*)(r0 + off);
    float4 a1 = *(const float4*)(r0 + off + NCOL);

    for (int i = 0; i < niter; ++i) {
        const int cur = i & 1;
        float v0[4] = {a0.x, a0.y, a0.z, a0.w};
        float v1[4] = {a1.x, a1.y, a1.z, a1.w};
#pragma unroll
        for (int j = 0; j < 4; ++j) {
            if (v0[j] == 0.0f) v0[j] = 1e-40f;
            if (v1[j] == 0.0f) v1[j] = 1e-40f;
        }
        float p0 = wredsum((v0[0] + v0[1]) + (v0[2] + v0[3]));
        float p1 = wredsum((v1[0] + v1[1]) + (v1[2] + v1[3]));
        if (lane == 0) { sp[cur][0][wid] = p0; sp[cur][1][wid] = p1; }

        if (i + 1 < niter) {        /* r0 has no padding — guard the prefetch */
            a0 = *(const float4*)(r0 + off + ds);
            a1 = *(const float4*)(r0 + off + ds + NCOL);
        }
        __syncthreads();
        float S0 = 0.f, S1 = 0.f;
#pragma unroll
        for (int w = 0; w < NWARP; ++w) { S0 += sp[cur][0][w]; S1 += sp[cur][1][w]; }
        const float i0 = __fdividef(1.0f, S0);
        const float i1 = __fdividef(1.0f, S1);

        float r0n[4], r1n[4], q0[4], q1[4];
#pragma unroll
        for (int j = 0; j < 4; ++j) {
            r0n[j] = v0[j] * i0;     r1n[j] = v1[j] * i1;
            q0[j]  = sqrt_ap(v0[j]); q1[j] = sqrt_ap(v1[j]);
        }
        st4h(g_u + PAD + off,        r0n);
        st4h(g_u + PAD + off + NCOL, r1n);
        st4h(g_h + PAD + off,        q0);
        st4h(g_h + PAD + off + NCOL, q1);
#pragma unroll
        for (int j = 0; j < 4; ++j) {
            float s0 = soft(r0n[j]), s1 = soft(r1n[j]);
            c4[j] += s0 * s0 + s1 * s1;
        }
        off += ds;
    }
#pragma unroll
    for (int j = 0; j < 4; ++j)
        atomicAdd(&g_cs[((size_t)1 * NCOL + col + j) * CSS], c4[j]);
}

// Step k: u_k -> u_{k+1}, colsum_{k+1}; LAST writes fp32 R_20 to out.
// e = sqrt(r0c) * (sqrt_ap(X) + 1e-20) * exp2(K2E * z)
template<int REV, int LAST>
__global__ void __launch_bounds__(NTHR, 4) k_step(float* __restrict__ out, int k) {
    __shared__ float sp[2][2][NWARP];
    const int tid  = threadIdx.x;
    const int lane = tid & 31;
    const int wid  = tid >> 5;
    const int col  = tid * 4;

    float sc[4];
#pragma unroll
    for (int j = 0; j < 4; ++j) {
        float cs = g_cs[((size_t)k * NCOL + col + j) * CSS];
        sc[j] = fmaxf(1.0f - SHRK / (sqrtf(cs) + EPSI), 0.0f);
    }

    float c4[4] = {0.f, 0.f, 0.f, 0.f};

    const int  pair0 = REV ? (NPAIR - 1 - blockIdx.x) : blockIdx.x;
    const int  niter = (NPAIR - blockIdx.x + GRID - 1) / GRID;
    const long long ds = (REV ? -(long long)GRID : (long long)GRID) * (2 * NCOL);
    long long off = (long long)pair0 * 2 * NCOL + col;

    const __half* pu = g_u + PAD;
    const __half* ph = g_h + PAD;

    uint2 ru0 = *(const uint2*)(pu + off);
    uint2 ru1 = *(const uint2*)(pu + off + NCOL);
    uint2 rh0 = *(const uint2*)(ph + off);
    uint2 rh1 = *(const uint2*)(ph + off + NCOL);

    for (int i = 0; i < niter; ++i) {
        const int cur = i & 1;

        float uu0[4], uu1[4], hh0[4], hh1[4];
        cvt4(ru0, uu0); cvt4(ru1, uu1);
        cvt4(rh0, hh0); cvt4(rh1, hh1);

        float e0[4], e1[4], zp0[4], zp1[4];
#pragma unroll
        for (int j = 0; j < 4; ++j) {
            float s  = soft(uu0[j]);
            float X  = sc[j] * s;
            zp0[j]   = uu0[j] - X;                          // Z_k
            float sx = sqrt_ap(X) + SQMIN;                  // branchless MIN_VALUE path
            e0[j]    = hh0[j] * sx * ex2(K2E * zp0[j]);
        }
#pragma unroll
        for (int j = 0; j < 4; ++j) {
            float s  = soft(uu1[j]);
            float X  = sc[j] * s;
            zp1[j]   = uu1[j] - X;
            float sx = sqrt_ap(X) + SQMIN;
            e1[j]    = hh1[j] * sx * ex2(K2E * zp1[j]);
        }
        float p0 = wredsum((e0[0] + e0[1]) + (e0[2] + e0[3]));
        float p1 = wredsum((e1[0] + e1[1]) + (e1[2] + e1[3]));
        if (lane == 0) { sp[cur][0][wid] = p0; sp[cur][1][wid] = p1; }

        /* unguarded prefetch — padding absorbs the final overshoot */
        ru0 = *(const uint2*)(pu + off + ds);
        ru1 = *(const uint2*)(pu + off + ds + NCOL);
        rh0 = *(const uint2*)(ph + off + ds);
        rh1 = *(const uint2*)(ph + off + ds + NCOL);

        __syncthreads();
        float S0 = 0.f, S1 = 0.f;
#pragma unroll
        for (int ww = 0; ww < NWARP; ++ww) { S0 += sp[cur][0][ww]; S1 += sp[cur][1][ww]; }
        const float i0 = __fdividef(1.0f, S0);
        const float i1 = __fdividef(1.0f, S1);

        float rn0[4], rn1[4];
#pragma unroll
        for (int j = 0; j < 4; ++j) { rn0[j] = e0[j] * i0; rn1[j] = e1[j] * i1; }

        if (LAST) {
            *(float4*)(out + off)        = make_float4(rn0[0], rn0[1], rn0[2], rn0[3]);
            *(float4*)(out + off + NCOL) = make_float4(rn1[0], rn1[1], rn1[2], rn1[3]);
        } else {
            float un0[4], un1[4];
#pragma unroll
            for (int j = 0; j < 4; ++j) {
                un0[j] = rn0[j] + zp0[j];                   // u_{k+1}
                un1[j] = rn1[j] + zp1[j];
                float s0 = soft(un0[j]), s1 = soft(un1[j]);
                c4[j] += s0 * s0 + s1 * s1;
            }
            st4h((__half*)(pu + off),        un0);
            st4h((__half*)(pu + off + NCOL), un1);
        }
        off += ds;
    }
    if (!LAST) {
#pragma unroll
        for (int j = 0; j < 4; ++j)
            atomicAdd(&g_cs[((size_t)(k + 1) * NCOL + col + j) * CSS], c4[j]);
    }
}

extern "C" void kernel_launch(void* const* d_in, const int* in_sizes, int n_in,
                              void* d_out, int out_size) {
    const float* r0 = (const float*)d_in[0];
    float* out = (float*)d_out;

    k_zero<<<NIT, NCOL>>>();
    k_init<<<GRID, NTHR>>>(r0);
    for (int k = 1; k < NIT; ++k) {
        const int rev  = k & 1;
        const int last = (k == NIT - 1);
        if (last) {
            if (rev) k_step<1, 1><<<GRID, NTHR>>>(out, k);
            else     k_step<0, 1><<<GRID, NTHR>>>(out, k);
        } else {
            if (rev) k_step<1, 0><<<GRID, NTHR>>>(out, k);
            else     k_step<0, 0><<<GRID, NTHR>>>(out, k);
        }
    }
}

// round 15
// speedup vs baseline: 1.0926x; 1.0092x over previous
#include <cuda_runtime.h>
#include <cuda_fp16.h>

#define NROWS 16384
#define NCOL  1024
#define NPAIR (NROWS / 2)     /* 8192 row pairs */
#define NTHR  256
#define NWARP (NTHR / 32)
#define GRID  592             /* 148 SMs x 4 CTAs, persistent */
#define NIT   20
#define CSS   64              /* colsum counter stride in floats (256 B) */
#define THR   0.05f           /* ALPHA*LAMBD/RHO */
#define SHRK  0.05f           /* (1-ALPHA)*LAMBD */
#define EPSI  1e-10f
#define SQMIN 1e-20f          /* sqrt(MIN_VALUE) */
#define K2E   (-0.72134752044448170f)  /* -0.5 * log2(e) */
#define PAD   (GRID * 2 * NCOL)   /* prefetch overshoot padding (elements) */

__device__ __half g_u[NROWS * NCOL + 2 * PAD];       /* fp16 u_k, padded both ends */
__device__ __half g_h[NROWS * NCOL + 2 * PAD];       /* fp16 sqrt(R_0c), padded */
__device__ float  g_cs[(size_t)NIT * NCOL * CSS];

__global__ void k_zero() {
    g_cs[((size_t)blockIdx.x * NCOL + threadIdx.x) * CSS] = 0.0f;
}

/* single-MUFU sqrt; sqrt.approx.f32(0) == 0 exactly (PTX ISA) */
__device__ __forceinline__ float sqrt_ap(float x) {
    float r;
    asm("sqrt.approx.f32 %0, %1;" : "=f"(r) : "f"(x));
    return r;
}

/* single-MUFU exp2 */
__device__ __forceinline__ float ex2(float x) {
    float r;
    asm("ex2.approx.f32 %0, %1;" : "=f"(r) : "f"(x));
    return r;
}

/* soft threshold as x - clamp(x, -THR, THR): 3 ops, exact */
__device__ __forceinline__ float soft(float x) {
    return x - fminf(fmaxf(x, -THR), THR);
}

__device__ __forceinline__ float wredsum(float v) {
#pragma unroll
    for (int o = 16; o > 0; o >>= 1) v += __shfl_xor_sync(0xffffffffu, v, o);
    return v;
}

__device__ __forceinline__ void cvt4(uint2 pk, float f[4]) {
    __half2 a = *reinterpret_cast<__half2*>(&pk.x);
    __half2 b = *reinterpret_cast<__half2*>(&pk.y);
    float2 fa = __half22float2(a), fb = __half22float2(b);
    f[0] = fa.x; f[1] = fa.y; f[2] = fb.x; f[3] = fb.y;
}

__device__ __forceinline__ void st4h(__half* p, const float f[4]) {
    __half2 a = __floats2half2_rn(f[0], f[1]);
    __half2 b = __floats2half2_rn(f[2], f[3]);
    uint2 pk;
    pk.x = *reinterpret_cast<unsigned*>(&a);
    pk.y = *reinterpret_cast<unsigned*>(&b);
    *(uint2*)p = pk;
}

// u_1 = R_1 = R_0c / rowsum(R_0c)  (Z_0 = 0); writes fp16 u_1, fp16 sqrt(R_0c); colsum_1.
__global__ void __launch_bounds__(NTHR, 4) k_init(const float* __restrict__ r0) {
    __shared__ float sp[2][2][NWARP];
    const int tid  = threadIdx.x;
    const int lane = tid & 31;
    const int wid  = tid >> 5;
    const int col  = tid * 4;

    float c4[4] = {0.f, 0.f, 0.f, 0.f};

    const int  niter = (NPAIR - blockIdx.x + GRID - 1) / GRID;
    const long long ds = (long long)GRID * 2 * NCOL;
    long long off = (long long)blockIdx.x * 2 * NCOL + col;

    float4 a0 = *(const float4*)(r0 + off);
    float4 a1 = *(const float4*)(r0 + off + NCOL);

    for (int i = 0; i < niter; ++i) {
        const int cur = i & 1;
        float v0[4] = {a0.x, a0.y, a0.z, a0.w};
        float v1[4] = {a1.x, a1.y, a1.z, a1.w};
#pragma unroll
        for (int j = 0; j < 4; ++j) {
            if (v0[j] == 0.0f) v0[j] = 1e-40f;
            if (v1[j] == 0.0f) v1[j] = 1e-40f;
        }
        float p0 = wredsum((v0[0] + v0[1]) + (v0[2] + v0[3]));
        float p1 = wredsum((v1[0] + v1[1]) + (v1[2] + v1[3]));
        if (lane == 0) { sp[cur][0][wid] = p0; sp[cur][1][wid] = p1; }

        if (i + 1 < niter) {        /* r0 has no padding — guard the prefetch */
            a0 = *(const float4*)(r0 + off + ds);
            a1 = *(const float4*)(r0 + off + ds + NCOL);
        }
        __syncthreads();
        float S0 = 0.f, S1 = 0.f;
#pragma unroll
        for (int w = 0; w < NWARP; ++w) { S0 += sp[cur][0][w]; S1 += sp[cur][1][w]; }
        const float i0 = __fdividef(1.0f, S0);
        const float i1 = __fdividef(1.0f, S1);

        float r0n[4], r1n[4], q0[4], q1[4];
#pragma unroll
        for (int j = 0; j < 4; ++j) {
            r0n[j] = v0[j] * i0;     r1n[j] = v1[j] * i1;
            q0[j]  = sqrt_ap(v0[j]); q1[j] = sqrt_ap(v1[j]);
        }
        st4h(g_u + PAD + off,        r0n);
        st4h(g_u + PAD + off + NCOL, r1n);
        st4h(g_h + PAD + off,        q0);
        st4h(g_h + PAD + off + NCOL, q1);
#pragma unroll
        for (int j = 0; j < 4; ++j) {
            float s0 = soft(r0n[j]), s1 = soft(r1n[j]);
            c4[j] += s0 * s0 + s1 * s1;
        }
        off += ds;
    }
#pragma unroll
    for (int j = 0; j < 4; ++j)
        atomicAdd(&g_cs[((size_t)1 * NCOL + col + j) * CSS], c4[j]);
}

// Step k: u_k -> u_{k+1}, colsum_{k+1}; LAST writes fp32 R_20 to out.
// e = sqrt(r0c) * (sqrt_ap(X) + 1e-20) * exp2(K2E * z)
template<int REV, int LAST>
__global__ void __launch_bounds__(NTHR, 4) k_step(float* __restrict__ out, int k) {
    __shared__ float sp[2][2][NWARP];
    const int tid  = threadIdx.x;
    const int lane = tid & 31;
    const int wid  = tid >> 5;
    const int col  = tid * 4;

    float sc[4];
#pragma unroll
    for (int j = 0; j < 4; ++j) {
        float cs = g_cs[((size_t)k * NCOL + col + j) * CSS];
        sc[j] = fmaxf(1.0f - SHRK / (sqrtf(cs) + EPSI), 0.0f);
    }

    float c4[4] = {0.f, 0.f, 0.f, 0.f};

    const int  pair0 = REV ? (NPAIR - 1 - blockIdx.x) : blockIdx.x;
    const int  niter = (NPAIR - blockIdx.x + GRID - 1) / GRID;
    const long long ds = (REV ? -(long long)GRID : (long long)GRID) * (2 * NCOL);
    long long off = (long long)pair0 * 2 * NCOL + col;

    const __half* pu = g_u + PAD;
    const __half* ph = g_h + PAD;

    uint2 ru0 = *(const uint2*)(pu + off);
    uint2 ru1 = *(const uint2*)(pu + off + NCOL);
    uint2 rh0 = *(const uint2*)(ph + off);
    uint2 rh1 = *(const uint2*)(ph + off + NCOL);

    for (int i = 0; i < niter; ++i) {
        const int cur = i & 1;

        float uu0[4], uu1[4], hh0[4], hh1[4];
        cvt4(ru0, uu0); cvt4(ru1, uu1);
        cvt4(rh0, hh0); cvt4(rh1, hh1);

        float e0[4], e1[4], zp0[4], zp1[4];
#pragma unroll
        for (int j = 0; j < 4; ++j) {
            float s  = soft(uu0[j]);
            float X  = sc[j] * s;
            zp0[j]   = uu0[j] - X;                          // Z_k
            float sx = sqrt_ap(X) + SQMIN;                  // branchless MIN_VALUE path
            e0[j]    = hh0[j] * sx * ex2(K2E * zp0[j]);
        }
#pragma unroll
        for (int j = 0; j < 4; ++j) {
            float s  = soft(uu1[j]);
            float X  = sc[j] * s;
            zp1[j]   = uu1[j] - X;
            float sx = sqrt_ap(X) + SQMIN;
            e1[j]    = hh1[j] * sx * ex2(K2E * zp1[j]);
        }
        float p0 = wredsum((e0[0] + e0[1]) + (e0[2] + e0[3]));
        float p1 = wredsum((e1[0] + e1[1]) + (e1[2] + e1[3]));
        if (lane == 0) { sp[cur][0][wid] = p0; sp[cur][1][wid] = p1; }

        /* unguarded prefetch — padding absorbs the final overshoot */
        ru0 = *(const uint2*)(pu + off + ds);
        ru1 = *(const uint2*)(pu + off + ds + NCOL);
        rh0 = *(const uint2*)(ph + off + ds);
        rh1 = *(const uint2*)(ph + off + ds + NCOL);

        __syncthreads();
        float S0 = 0.f, S1 = 0.f;
#pragma unroll
        for (int ww = 0; ww < NWARP; ++ww) { S0 += sp[cur][0][ww]; S1 += sp[cur][1][ww]; }
        const float i0 = __fdividef(1.0f, S0);
        const float i1 = __fdividef(1.0f, S1);

        float rn0[4], rn1[4];
#pragma unroll
        for (int j = 0; j < 4; ++j) { rn0[j] = e0[j] * i0; rn1[j] = e1[j] * i1; }

        if (LAST) {
            *(float4*)(out + off)        = make_float4(rn0[0], rn0[1], rn0[2], rn0[3]);
            *(float4*)(out + off + NCOL) = make_float4(rn1[0], rn1[1], rn1[2], rn1[3]);
        } else {
            float un0[4], un1[4];
#pragma unroll
            for (int j = 0; j < 4; ++j) {
                un0[j] = rn0[j] + zp0[j];                   // u_{k+1}
                un1[j] = rn1[j] + zp1[j];
                float s0 = soft(un0[j]), s1 = soft(un1[j]);
                c4[j] += s0 * s0 + s1 * s1;
            }
            st4h((__half*)(pu + off),        un0);
            st4h((__half*)(pu + off + NCOL), un1);
        }
        off += ds;
    }
    if (!LAST) {
#pragma unroll
        for (int j = 0; j < 4; ++j)
            atomicAdd(&g_cs[((size_t)(k + 1) * NCOL + col + j) * CSS], c4[j]);
    }
}

extern "C" void kernel_launch(void* const* d_in, const int* in_sizes, int n_in,
                              void* d_out, int out_size) {
    const float* r0 = (const float*)d_in[0];
    float* out = (float*)d_out;

    k_zero<<<NIT, NCOL>>>();
    k_init<<<GRID, NTHR>>>(r0);
    for (int k = 1; k < NIT; ++k) {
        const int rev  = k & 1;
        const int last = (k == NIT - 1);
        if (last) {
            if (rev) k_step<1, 1><<<GRID, NTHR>>>(out, k);
            else     k_step<0, 1><<<GRID, NTHR>>>(out, k);
        } else {
            if (rev) k_step<1, 0><<<GRID, NTHR>>>(out, k);
            else     k_step<0, 0><<<GRID, NTHR>>>(out, k);
        }
    }
}